// round 6
// baseline (speedup 1.0000x reference)
#include <cuda_runtime.h>
#include <cuda_bf16.h>
#include <cstdint>

// Problem constants
#define Bsz   8
#define Npts  16384
#define Spts  1024
#define Dfeat 256
#define CIN   512
#define CMID  256
#define COUT  256
#define CNT_INV (1.0f / (8.0f * 16384.0f))

// ---------------- scratch (device globals; no runtime allocation) ----------------
__device__ float g_p2t[Bsz * Spts * Dfeat];          // points2 transposed [B,S,D]  (8 MB)
__device__ float g_w3 [Bsz * Npts * 3];              // interp weights
__device__ int   g_i3 [Bsz * Npts * 3];              // interp indices
__device__ float g_interp[Bsz * Dfeat * Npts];       // interpolated feats [B,D,N] (134 MB)
__device__ float g_y0[Bsz * CMID * Npts];            // GEMM1 raw output            (134 MB)
__device__ float g_sum0[CMID], g_sq0[CMID], g_sum1[COUT], g_sq1[COUT];
__device__ float g_a0[CMID], g_be0[CMID], g_a1[COUT], g_be1[COUT];

// ---------------- f32x2 packed helpers ----------------
__device__ __forceinline__ unsigned long long pack2(float lo, float hi) {
    unsigned long long r;
    asm("mov.b64 %0, {%1, %2};" : "=l"(r) : "f"(lo), "f"(hi));
    return r;
}
__device__ __forceinline__ void unpack2(unsigned long long v, float& lo, float& hi) {
    asm("mov.b64 {%0, %1}, %2;" : "=f"(lo), "=f"(hi) : "l"(v));
}
__device__ __forceinline__ unsigned long long ffma2(unsigned long long a,
                                                    unsigned long long b,
                                                    unsigned long long c) {
    unsigned long long d;
    asm("fma.rn.f32x2 %0, %1, %2, %3;" : "=l"(d) : "l"(a), "l"(b), "l"(c));
    return d;
}

// ---------------- 1) transpose points2 [B,D,S] -> [B,S,D] ----------------
__global__ void transpose_p2_kernel(const float* __restrict__ p2) {
    __shared__ float t[32][33];
    int b  = blockIdx.z;
    int s0 = blockIdx.x * 32, d0 = blockIdx.y * 32;
    int tx = threadIdx.x, ty = threadIdx.y;          // 32 x 8
    const float* src = p2 + (size_t)b * Dfeat * Spts;
#pragma unroll
    for (int j = 0; j < 32; j += 8)
        t[ty + j][tx] = src[(size_t)(d0 + ty + j) * Spts + s0 + tx];
    __syncthreads();
    float* dst = g_p2t + (size_t)b * Spts * Dfeat;
#pragma unroll
    for (int j = 0; j < 32; j += 8)
        dst[(size_t)(s0 + ty + j) * Dfeat + d0 + tx] = t[tx][ty + j];
}

// ---------------- 2) 3-NN search + weights ----------------
__global__ void knn_kernel(const float* __restrict__ xyz1, const float* __restrict__ xyz2) {
    __shared__ float sx[Spts], sy[Spts], sz[Spts], sn[Spts];
    int b = blockIdx.y;
    int n = blockIdx.x * blockDim.x + threadIdx.x;
    const float* x2 = xyz2 + (size_t)b * 3 * Spts;
    for (int s = threadIdx.x; s < Spts; s += blockDim.x) {
        float X = x2[s], Y = x2[Spts + s], Z = x2[2 * Spts + s];
        sx[s] = X; sy[s] = Y; sz[s] = Z;
        sn[s] = X * X + Y * Y + Z * Z;
    }
    __syncthreads();
    const float* x1 = xyz1 + (size_t)b * 3 * Npts;
    float px = x1[n], py = x1[Npts + n], pz = x1[2 * Npts + n];
    float n1 = px * px + py * py + pz * pz;
    float d0 = 3.4e38f, d1 = 3.4e38f, d2 = 3.4e38f;
    int   i0 = 0, i1 = 0, i2 = 0;
#pragma unroll 4
    for (int s = 0; s < Spts; s++) {
        float dot = px * sx[s] + py * sy[s] + pz * sz[s];
        float d   = n1 - 2.0f * dot + sn[s];         // same formula as reference
        if (d < d2) {
            if (d < d1) {
                d2 = d1; i2 = i1;
                if (d < d0) { d1 = d0; i1 = i0; d0 = d; i0 = s; }
                else        { d1 = d;  i1 = s; }
            } else { d2 = d; i2 = s; }
        }
    }
    float r0 = 1.0f / (d0 + 1e-8f);
    float r1 = 1.0f / (d1 + 1e-8f);
    float r2 = 1.0f / (d2 + 1e-8f);
    float rs = 1.0f / (r0 + r1 + r2);
    int o = (b * Npts + n) * 3;
    g_w3[o] = r0 * rs; g_w3[o + 1] = r1 * rs; g_w3[o + 2] = r2 * rs;
    g_i3[o] = i0;      g_i3[o + 1] = i1;      g_i3[o + 2] = i2;
}

// ---------------- 3) interpolation: g_interp[b][d][n] ----------------
__global__ void interp_kernel() {
    __shared__ float tile[256 * 33];
    int b   = blockIdx.y;
    int n0  = blockIdx.x * 32;
    int tid = threadIdx.x, lane = tid & 31, wid = tid >> 5;
#pragma unroll
    for (int p = 0; p < 4; p++) {
        int nloc = wid * 4 + p;
        int n    = n0 + nloc;
        int base = (b * Npts + n) * 3;
        float w0 = g_w3[base], w1 = g_w3[base + 1], w2 = g_w3[base + 2];
        const float* r0 = g_p2t + ((size_t)b * Spts + g_i3[base])     * Dfeat;
        const float* r1 = g_p2t + ((size_t)b * Spts + g_i3[base + 1]) * Dfeat;
        const float* r2 = g_p2t + ((size_t)b * Spts + g_i3[base + 2]) * Dfeat;
#pragma unroll
        for (int j = 0; j < 8; j++) {
            int d = lane + 32 * j;
            float v = w0 * r0[d] + w1 * r1[d] + w2 * r2[d];
            tile[d * 33 + nloc] = v;
        }
    }
    __syncthreads();
    float* outb = g_interp + (size_t)b * Dfeat * Npts;
#pragma unroll 4
    for (int e = tid; e < 256 * 32; e += 256) {
        int d = e >> 5, nl = e & 31;
        outb[(size_t)d * Npts + n0 + nl] = tile[d * 33 + nl];
    }
}

// ---------------- stats zero / reduce / finalize ----------------
__global__ void zero_stats_kernel() {
    int t = threadIdx.x;
    g_sum0[t] = 0.f; g_sq0[t] = 0.f; g_sum1[t] = 0.f; g_sq1[t] = 0.f;
}

__device__ __forceinline__ void stats_reduce(const float* __restrict__ p,
                                             float* __restrict__ sum, float* __restrict__ sq, int c) {
    float s = 0.f, s2 = 0.f;
    for (int i = threadIdx.x; i < Npts; i += 256) {
        float v = p[i];
        s += v; s2 += v * v;
    }
#pragma unroll
    for (int o = 16; o; o >>= 1) {
        s  += __shfl_down_sync(0xffffffffu, s, o);
        s2 += __shfl_down_sync(0xffffffffu, s2, o);
    }
    __shared__ float ss[8], ss2[8];
    if ((threadIdx.x & 31) == 0) { ss[threadIdx.x >> 5] = s; ss2[threadIdx.x >> 5] = s2; }
    __syncthreads();
    if (threadIdx.x == 0) {
        float t = 0.f, t2 = 0.f;
#pragma unroll
        for (int i = 0; i < 8; i++) { t += ss[i]; t2 += ss2[i]; }
        atomicAdd(sum + c, t);
        atomicAdd(sq + c, t2);
    }
}

__global__ void stats_y0_kernel() {
    int c = blockIdx.x, b = blockIdx.y;
    stats_reduce(g_y0 + ((size_t)b * CMID + c) * Npts, g_sum0, g_sq0, c);
}
__global__ void stats_out_kernel(const float* __restrict__ out) {
    int c = blockIdx.x, b = blockIdx.y;
    stats_reduce(out + ((size_t)b * COUT + c) * Npts, g_sum1, g_sq1, c);
}

__global__ void finalize0_kernel(const float* __restrict__ g, const float* __restrict__ be) {
    int c = threadIdx.x;
    float mean = g_sum0[c] * CNT_INV;
    float var  = g_sq0[c] * CNT_INV - mean * mean;
    float inv  = rsqrtf(var + 1e-5f);
    float a    = g[c] * inv;
    g_a0[c] = a; g_be0[c] = be[c] - mean * a;
}
__global__ void finalize1_kernel(const float* __restrict__ g, const float* __restrict__ be) {
    int c = threadIdx.x;
    float mean = g_sum1[c] * CNT_INV;
    float var  = g_sq1[c] * CNT_INV - mean * mean;
    float inv  = rsqrtf(var + 1e-5f);
    float a    = g[c] * inv;
    g_a1[c] = a; g_be1[c] = be[c] - mean * a;
}

// ---------------- GEMM1: y0 = W0[256x512] @ X[512xN] + b0 (per batch) ----------------
// X rows 0..255 = points1[b], rows 256..511 = g_interp[b]. 128x128x8 tiles, 8x8/thread, f32x2 FMA.
__global__ __launch_bounds__(256, 2)
void gemm1_kernel(const float* __restrict__ w0, const float* __restrict__ b0,
                  const float* __restrict__ p1) {
    __shared__ float As[8][128];
    __shared__ float Bs[8][128];
    int b   = blockIdx.z;
    int n0  = blockIdx.x * 128;
    int m0  = blockIdx.y * 128;
    int tid = threadIdx.x;
    int tx  = tid & 15, ty = tid >> 4;

    const float* Xa = p1       + (size_t)b * Dfeat * Npts;
    const float* Xb = g_interp + (size_t)b * Dfeat * Npts;

    unsigned long long acc[8][4];
#pragma unroll
    for (int j = 0; j < 8; j++)
#pragma unroll
        for (int i = 0; i < 4; i++) acc[j][i] = 0ULL;

    int la_r = tid >> 1, la_k = (tid & 1) * 4;   // A: 128 rows x 8 k
    int lb_k = tid >> 5, lb_c = (tid & 31) * 4;  // B: 8 k x 128 cols

    for (int k0 = 0; k0 < CIN; k0 += 8) {
        float4 av = *(const float4*)(w0 + (size_t)(m0 + la_r) * CIN + k0 + la_k);
        const float* src = (k0 < Dfeat) ? (Xa + (size_t)k0 * Npts)
                                        : (Xb + (size_t)(k0 - Dfeat) * Npts);
        float4 bv = *(const float4*)(src + (size_t)lb_k * Npts + n0 + lb_c);
        __syncthreads();
        As[la_k + 0][la_r] = av.x; As[la_k + 1][la_r] = av.y;
        As[la_k + 2][la_r] = av.z; As[la_k + 3][la_r] = av.w;
        *(float4*)&Bs[lb_k][lb_c] = bv;
        __syncthreads();
#pragma unroll
        for (int kk = 0; kk < 8; kk++) {
            float4 a0 = *(const float4*)&As[kk][ty * 8];
            float4 a1 = *(const float4*)&As[kk][ty * 8 + 4];
            const unsigned long long* B64 = (const unsigned long long*)&Bs[kk][tx * 8];
            unsigned long long bq0 = B64[0], bq1 = B64[1], bq2 = B64[2], bq3 = B64[3];
            float aa[8] = {a0.x, a0.y, a0.z, a0.w, a1.x, a1.y, a1.z, a1.w};
#pragma unroll
            for (int j = 0; j < 8; j++) {
                unsigned long long ad = pack2(aa[j], aa[j]);
                acc[j][0] = ffma2(ad, bq0, acc[j][0]);
                acc[j][1] = ffma2(ad, bq1, acc[j][1]);
                acc[j][2] = ffma2(ad, bq2, acc[j][2]);
                acc[j][3] = ffma2(ad, bq3, acc[j][3]);
            }
        }
    }
#pragma unroll
    for (int j = 0; j < 8; j++) {
        int o = m0 + ty * 8 + j;
        float bias = b0[o];
        float v[8];
#pragma unroll
        for (int i = 0; i < 4; i++) unpack2(acc[j][i], v[2 * i], v[2 * i + 1]);
        float4 o0 = {v[0] + bias, v[1] + bias, v[2] + bias, v[3] + bias};
        float4 o1 = {v[4] + bias, v[5] + bias, v[6] + bias, v[7] + bias};
        float* dst = g_y0 + ((size_t)b * CMID + o) * Npts + n0 + tx * 8;
        *(float4*)dst       = o0;
        *(float4*)(dst + 4) = o1;
    }
}

// ---------------- GEMM2: out_raw = W1[256x256] @ relu(BN1(y0)) + b1 ----------------
__global__ __launch_bounds__(256, 2)
void gemm2_kernel(const float* __restrict__ w1, const float* __restrict__ b1,
                  float* __restrict__ out) {
    __shared__ float As[8][128];
    __shared__ float Bs[8][128];
    int b   = blockIdx.z;
    int n0  = blockIdx.x * 128;
    int m0  = blockIdx.y * 128;
    int tid = threadIdx.x;
    int tx  = tid & 15, ty = tid >> 4;

    const float* Y = g_y0 + (size_t)b * CMID * Npts;

    unsigned long long acc[8][4];
#pragma unroll
    for (int j = 0; j < 8; j++)
#pragma unroll
        for (int i = 0; i < 4; i++) acc[j][i] = 0ULL;

    int la_r = tid >> 1, la_k = (tid & 1) * 4;
    int lb_k = tid >> 5, lb_c = (tid & 31) * 4;

    for (int k0 = 0; k0 < CMID; k0 += 8) {
        float4 av = *(const float4*)(w1 + (size_t)(m0 + la_r) * CMID + k0 + la_k);
        int kr = k0 + lb_k;
        float a0v = g_a0[kr], be0v = g_be0[kr];
        float4 bv = *(const float4*)(Y + (size_t)kr * Npts + n0 + lb_c);
        bv.x = fmaxf(fmaf(a0v, bv.x, be0v), 0.f);
        bv.y = fmaxf(fmaf(a0v, bv.y, be0v), 0.f);
        bv.z = fmaxf(fmaf(a0v, bv.z, be0v), 0.f);
        bv.w = fmaxf(fmaf(a0v, bv.w, be0v), 0.f);
        __syncthreads();
        As[la_k + 0][la_r] = av.x; As[la_k + 1][la_r] = av.y;
        As[la_k + 2][la_r] = av.z; As[la_k + 3][la_r] = av.w;
        *(float4*)&Bs[lb_k][lb_c] = bv;
        __syncthreads();
#pragma unroll
        for (int kk = 0; kk < 8; kk++) {
            float4 a0 = *(const float4*)&As[kk][ty * 8];
            float4 a1 = *(const float4*)&As[kk][ty * 8 + 4];
            const unsigned long long* B64 = (const unsigned long long*)&Bs[kk][tx * 8];
            unsigned long long bq0 = B64[0], bq1 = B64[1], bq2 = B64[2], bq3 = B64[3];
            float aa[8] = {a0.x, a0.y, a0.z, a0.w, a1.x, a1.y, a1.z, a1.w};
#pragma unroll
            for (int j = 0; j < 8; j++) {
                unsigned long long ad = pack2(aa[j], aa[j]);
                acc[j][0] = ffma2(ad, bq0, acc[j][0]);
                acc[j][1] = ffma2(ad, bq1, acc[j][1]);
                acc[j][2] = ffma2(ad, bq2, acc[j][2]);
                acc[j][3] = ffma2(ad, bq3, acc[j][3]);
            }
        }
    }
#pragma unroll
    for (int j = 0; j < 8; j++) {
        int o = m0 + ty * 8 + j;
        float bias = b1[o];
        float v[8];
#pragma unroll
        for (int i = 0; i < 4; i++) unpack2(acc[j][i], v[2 * i], v[2 * i + 1]);
        float4 o0 = {v[0] + bias, v[1] + bias, v[2] + bias, v[3] + bias};
        float4 o1 = {v[4] + bias, v[5] + bias, v[6] + bias, v[7] + bias};
        float* dst = out + ((size_t)b * COUT + o) * Npts + n0 + tx * 8;
        *(float4*)dst       = o0;
        *(float4*)(dst + 4) = o1;
    }
}

// ---------------- final BN2 + ReLU in place on d_out ----------------
__global__ void bnrelu_kernel(float* __restrict__ out) {
    size_t i = (size_t)blockIdx.x * 256 + threadIdx.x;        // float4 index
    int c = (int)((i / (Npts / 4)) & (COUT - 1));
    float a = g_a1[c], be = g_be1[c];
    float4 v = ((float4*)out)[i];
    v.x = fmaxf(fmaf(a, v.x, be), 0.f);
    v.y = fmaxf(fmaf(a, v.y, be), 0.f);
    v.z = fmaxf(fmaf(a, v.z, be), 0.f);
    v.w = fmaxf(fmaf(a, v.w, be), 0.f);
    ((float4*)out)[i] = v;
}

// ---------------- launch ----------------
extern "C" void kernel_launch(void* const* d_in, const int* in_sizes, int n_in,
                              void* d_out, int out_size) {
    const float* xyz1    = (const float*)d_in[0];
    const float* xyz2    = (const float*)d_in[1];
    const float* points1 = (const float*)d_in[2];
    const float* points2 = (const float*)d_in[3];
    const float* w0      = (const float*)d_in[4];
    const float* b0      = (const float*)d_in[5];
    const float* g0      = (const float*)d_in[6];
    const float* be0     = (const float*)d_in[7];
    const float* w1      = (const float*)d_in[8];
    const float* b1      = (const float*)d_in[9];
    const float* g1      = (const float*)d_in[10];
    const float* be1     = (const float*)d_in[11];
    float* out = (float*)d_out;

    transpose_p2_kernel<<<dim3(Spts / 32, Dfeat / 32, Bsz), dim3(32, 8)>>>(points2);
    knn_kernel<<<dim3(Npts / 256, Bsz), 256>>>(xyz1, xyz2);
    interp_kernel<<<dim3(Npts / 32, Bsz), 256>>>();
    zero_stats_kernel<<<1, 256>>>();
    gemm1_kernel<<<dim3(Npts / 128, CMID / 128, Bsz), 256>>>(w0, b0, points1);
    stats_y0_kernel<<<dim3(CMID, Bsz), 256>>>();
    finalize0_kernel<<<1, CMID>>>(g0, be0);
    gemm2_kernel<<<dim3(Npts / 128, COUT / 128, Bsz), 256>>>(w1, b1, out);
    stats_out_kernel<<<dim3(COUT, Bsz), 256>>>(out);
    finalize1_kernel<<<1, COUT>>>(g1, be1);
    bnrelu_kernel<<<(Bsz * COUT * Npts / 4) / 256, 256>>>(out);
}

// round 10
// speedup vs baseline: 2.1355x; 2.1355x over previous
#include <cuda_runtime.h>
#include <cuda_bf16.h>
#include <cstdint>

#define Bsz   8
#define Npts  16384
#define Spts  1024
#define Dfeat 256
#define CIN   512
#define CMID  256
#define COUT  256
#define CNT_INV (1.0f / (8.0f * 16384.0f))

// ---------------- scratch (device globals; no runtime allocation) ----------------
__device__ __align__(128) float g_p2t[Bsz * Spts * Dfeat];            // points2^T [B,S,D]
__device__ float g_w3[Bsz * Npts * 3];
__device__ int   g_i3[Bsz * Npts * 3];
__device__ __align__(128) float g_interp[(size_t)Bsz * Dfeat * Npts]; // [B,D,N]
__device__ __align__(128) float g_y0[(size_t)Bsz * CMID * Npts];      // raw GEMM1 out
__device__ __align__(128) __nv_bfloat16 g_w0h[CMID * CIN], g_w0l[CMID * CIN];
__device__ __align__(128) __nv_bfloat16 g_w1h[COUT * CMID], g_w1l[COUT * CMID];
__device__ float g_sum0[CMID], g_sq0[CMID], g_sum1[COUT], g_sq1[COUT];
__device__ float g_a0[CMID], g_be0[CMID], g_a1[COUT], g_be1[COUT];

// ---------------- helpers ----------------
__device__ __forceinline__ uint32_t smem_u32(const void* p) {
    uint32_t a;
    asm("{ .reg .u64 t; cvta.to.shared.u64 t, %1; cvt.u32.u64 %0, t; }" : "=r"(a) : "l"(p));
    return a;
}
#define LDSM4(R, A) \
    asm volatile("ldmatrix.sync.aligned.m8n8.x4.shared.b16 {%0,%1,%2,%3}, [%4];" \
        : "=r"((R)[0]), "=r"((R)[1]), "=r"((R)[2]), "=r"((R)[3]) : "r"(A))
#define LDSM4T(R, A) \
    asm volatile("ldmatrix.sync.aligned.m8n8.x4.trans.shared.b16 {%0,%1,%2,%3}, [%4];" \
        : "=r"((R)[0]), "=r"((R)[1]), "=r"((R)[2]), "=r"((R)[3]) : "r"(A))
#define MMA16816(C, A, B0, B1) \
    asm volatile("mma.sync.aligned.m16n8k16.row.col.f32.bf16.bf16.f32 " \
        "{%0,%1,%2,%3}, {%4,%5,%6,%7}, {%8,%9}, {%0,%1,%2,%3};" \
        : "+f"((C)[0]), "+f"((C)[1]), "+f"((C)[2]), "+f"((C)[3]) \
        : "r"((A)[0]), "r"((A)[1]), "r"((A)[2]), "r"((A)[3]), "r"(B0), "r"(B1))

// ---------------- transpose points2 [B,D,S] -> [B,S,D] ----------------
__global__ void transpose_p2_kernel(const float* __restrict__ p2) {
    __shared__ float t[32][33];
    int b = blockIdx.z, s0 = blockIdx.x * 32, d0 = blockIdx.y * 32;
    int tx = threadIdx.x, ty = threadIdx.y;
    const float* src = p2 + (size_t)b * Dfeat * Spts;
#pragma unroll
    for (int j = 0; j < 32; j += 8)
        t[ty + j][tx] = src[(size_t)(d0 + ty + j) * Spts + s0 + tx];
    __syncthreads();
    float* dst = g_p2t + (size_t)b * Spts * Dfeat;
#pragma unroll
    for (int j = 0; j < 32; j += 8)
        dst[(size_t)(s0 + ty + j) * Dfeat + d0 + tx] = t[tx][ty + j];
}

// ---------------- 3-NN + inverse-distance weights ----------------
__global__ void knn_kernel(const float* __restrict__ xyz1, const float* __restrict__ xyz2) {
    __shared__ float sx[Spts], sy[Spts], sz[Spts], sn[Spts];
    int b = blockIdx.y;
    int n = blockIdx.x * blockDim.x + threadIdx.x;
    const float* x2 = xyz2 + (size_t)b * 3 * Spts;
    for (int s = threadIdx.x; s < Spts; s += blockDim.x) {
        float X = x2[s], Y = x2[Spts + s], Z = x2[2 * Spts + s];
        sx[s] = X; sy[s] = Y; sz[s] = Z;
        sn[s] = X * X + Y * Y + Z * Z;
    }
    __syncthreads();
    const float* x1 = xyz1 + (size_t)b * 3 * Npts;
    float px = x1[n], py = x1[Npts + n], pz = x1[2 * Npts + n];
    float n1 = px * px + py * py + pz * pz;
    float d0 = 3.4e38f, d1 = 3.4e38f, d2 = 3.4e38f;
    int   i0 = 0, i1 = 0, i2 = 0;
#pragma unroll 4
    for (int s = 0; s < Spts; s++) {
        float d = n1 - 2.0f * (px * sx[s] + py * sy[s] + pz * sz[s]) + sn[s];
        if (d < d2) {
            if (d < d1) {
                d2 = d1; i2 = i1;
                if (d < d0) { d1 = d0; i1 = i0; d0 = d; i0 = s; }
                else        { d1 = d;  i1 = s; }
            } else { d2 = d; i2 = s; }
        }
    }
    float r0 = 1.0f / (d0 + 1e-8f), r1 = 1.0f / (d1 + 1e-8f), r2 = 1.0f / (d2 + 1e-8f);
    float rs = 1.0f / (r0 + r1 + r2);
    int o = (b * Npts + n) * 3;
    g_w3[o] = r0 * rs; g_w3[o + 1] = r1 * rs; g_w3[o + 2] = r2 * rs;
    g_i3[o] = i0;      g_i3[o + 1] = i1;      g_i3[o + 2] = i2;
}

// ---------------- interpolation -> g_interp [B,D,N] ----------------
__global__ void interp_kernel() {
    __shared__ float tile[256 * 33];
    int b   = blockIdx.y;
    int n0  = blockIdx.x * 32;
    int tid = threadIdx.x, lane = tid & 31, wid = tid >> 5;
#pragma unroll
    for (int p = 0; p < 4; p++) {
        int nloc = wid * 4 + p;
        int n    = n0 + nloc;
        int base = (b * Npts + n) * 3;
        float w0 = g_w3[base], w1 = g_w3[base + 1], w2 = g_w3[base + 2];
        const float* r0 = g_p2t + ((size_t)b * Spts + g_i3[base])     * Dfeat;
        const float* r1 = g_p2t + ((size_t)b * Spts + g_i3[base + 1]) * Dfeat;
        const float* r2 = g_p2t + ((size_t)b * Spts + g_i3[base + 2]) * Dfeat;
#pragma unroll
        for (int j = 0; j < 8; j++) {
            int d = lane + 32 * j;
            tile[d * 33 + nloc] = w0 * r0[d] + w1 * r1[d] + w2 * r2[d];
        }
    }
    __syncthreads();
    float* outb = g_interp + (size_t)b * Dfeat * Npts;
#pragma unroll 4
    for (int e = tid; e < 256 * 32; e += 256) {
        int d = e >> 5, nl = e & 31;
        outb[(size_t)d * Npts + n0 + nl] = tile[d * 33 + nl];
    }
}

// ---------------- weight split fp32 -> bf16 hi/lo ----------------
__global__ void split_w_kernel(const float* __restrict__ src, int which, int n) {
    int i = blockIdx.x * 256 + threadIdx.x;
    if (i >= n) return;
    float v = src[i];
    __nv_bfloat16 h = __float2bfloat16(v);
    __nv_bfloat16 l = __float2bfloat16(v - __bfloat162float(h));
    if (which) { g_w1h[i] = h; g_w1l[i] = l; }
    else       { g_w0h[i] = h; g_w0l[i] = l; }
}

// ---------------- stats zero / finalize ----------------
__global__ void zero_stats_kernel() {
    int t = threadIdx.x;
    g_sum0[t] = 0.f; g_sq0[t] = 0.f; g_sum1[t] = 0.f; g_sq1[t] = 0.f;
}
__global__ void finalize0_kernel(const float* __restrict__ g, const float* __restrict__ be) {
    int c = threadIdx.x;
    float mean = g_sum0[c] * CNT_INV;
    float var  = g_sq0[c] * CNT_INV - mean * mean;
    float a    = g[c] * rsqrtf(var + 1e-5f);
    g_a0[c] = a; g_be0[c] = be[c] - mean * a;
}
__global__ void finalize1_kernel(const float* __restrict__ g, const float* __restrict__ be) {
    int c = threadIdx.x;
    float mean = g_sum1[c] * CNT_INV;
    float var  = g_sq1[c] * CNT_INV - mean * mean;
    float a    = g[c] * rsqrtf(var + 1e-5f);
    g_a1[c] = a; g_be1[c] = be[c] - mean * a;
}

// ---------------- bf16x3 HMMA GEMM ----------------
// out[M=256, N=16384] = W @ X per batch. CTA tile 128M x 128N, K-chunk 32.
// which=0: X rows = points1 (0-255) / g_interp (256-511), dst = g_y0, stats0.
// which=1: X rows = relu(bn1(g_y0)), dst = outp, stats1.
#define APAD 40
#define BPAD 136
__global__ __launch_bounds__(256, 2)
void gemm_mma_kernel(int which, const float* __restrict__ p1, float* __restrict__ outp) {
    __shared__ __nv_bfloat16 sAh[128 * APAD];
    __shared__ __nv_bfloat16 sAl[128 * APAD];
    __shared__ __nv_bfloat16 sBh[32 * BPAD];
    __shared__ __nv_bfloat16 sBl[32 * BPAD];

    const int K   = which ? CMID : CIN;
    const int tid = threadIdx.x;
    const int lane = tid & 31, warp = tid >> 5;
    const int b  = blockIdx.z;
    const int n0 = blockIdx.x * 128;
    const int m0 = blockIdx.y * 128;
    const int wm = (warp >> 1) * 32;
    const int wn = (warp & 1) * 64;

    const __nv_bfloat16* Wh = which ? g_w1h : g_w0h;
    const __nv_bfloat16* Wl = which ? g_w1l : g_w0l;
    float* dst = which ? outp   : g_y0;
    float* sum = which ? g_sum1 : g_sum0;
    float* sq  = which ? g_sq1  : g_sq0;

    float acc[2][8][4];
#pragma unroll
    for (int t = 0; t < 2; t++)
#pragma unroll
        for (int j = 0; j < 8; j++)
#pragma unroll
            for (int q = 0; q < 4; q++) acc[t][j][q] = 0.f;

    const uint32_t uAh = smem_u32(sAh), uAl = smem_u32(sAl);
    const uint32_t uBh = smem_u32(sBh), uBl = smem_u32(sBl);
    const int a_row = wm + (lane & 15);
    const int a_col = (lane >> 4) * 8;
    const int b_row = (lane & 15);
    const int b_col = wn + (lane >> 4) * 8;

    for (int k0 = 0; k0 < K; k0 += 32) {
        __syncthreads();
        // ---- stage A (weights, already bf16 hi/lo) ----
#pragma unroll
        for (int i = 0; i < 2; i++) {
            int idx = i * 256 + tid;
            int r = idx >> 2, q = (idx & 3) * 8;
            size_t go = (size_t)(m0 + r) * K + k0 + q;
            *(uint4*)&sAh[r * APAD + q] = *(const uint4*)(Wh + go);
            *(uint4*)&sAl[r * APAD + q] = *(const uint4*)(Wl + go);
        }
        // ---- stage B: fp32 load (+BN1/ReLU for GEMM2), split to bf16 hi/lo ----
#pragma unroll
        for (int i = 0; i < 2; i++) {
            int idx = i * 256 + tid;
            int r = idx >> 4, c = (idx & 15) * 8;
            int k = k0 + r;
            const float* src;
            float sa = 1.f, sb = 0.f;
            if (which) {
                src = g_y0 + ((size_t)b * CMID + k) * Npts;
                sa = g_a0[k]; sb = g_be0[k];
            } else {
                src = (k < Dfeat) ? p1 + ((size_t)b * Dfeat + k) * Npts
                                  : g_interp + ((size_t)b * Dfeat + (k - Dfeat)) * Npts;
            }
            float4 v0 = *(const float4*)(src + n0 + c);
            float4 v1 = *(const float4*)(src + n0 + c + 4);
            float f[8] = {v0.x, v0.y, v0.z, v0.w, v1.x, v1.y, v1.z, v1.w};
            uint32_t hh[4], ll[4];
#pragma unroll
            for (int j = 0; j < 4; j++) {
                float x0 = f[2 * j], x1 = f[2 * j + 1];
                if (which) {
                    x0 = fmaxf(fmaf(sa, x0, sb), 0.f);
                    x1 = fmaxf(fmaf(sa, x1, sb), 0.f);
                }
                __nv_bfloat162 h2 = __floats2bfloat162_rn(x0, x1);
                __nv_bfloat162 l2 = __floats2bfloat162_rn(x0 - __bfloat162float(h2.x),
                                                          x1 - __bfloat162float(h2.y));
                hh[j] = *(uint32_t*)&h2;
                ll[j] = *(uint32_t*)&l2;
            }
            *(uint4*)&sBh[r * BPAD + c] = make_uint4(hh[0], hh[1], hh[2], hh[3]);
            *(uint4*)&sBl[r * BPAD + c] = make_uint4(ll[0], ll[1], ll[2], ll[3]);
        }
        __syncthreads();
        // ---- MMA: Ah*Bh + Al*Bh + Ah*Bl ----
#pragma unroll
        for (int ks = 0; ks < 2; ks++) {
            uint32_t ah[2][4], al[2][4];
#pragma unroll
            for (int t = 0; t < 2; t++) {
                uint32_t adr = uAh + (uint32_t)(((a_row + t * 16) * APAD + ks * 16 + a_col) * 2);
                LDSM4(ah[t], adr);
                adr = uAl + (uint32_t)(((a_row + t * 16) * APAD + ks * 16 + a_col) * 2);
                LDSM4(al[t], adr);
            }
#pragma unroll
            for (int jn = 0; jn < 4; jn++) {
                uint32_t bh[4], bl[4];
                uint32_t badr = uBh + (uint32_t)(((ks * 16 + b_row) * BPAD + b_col + jn * 16) * 2);
                LDSM4T(bh, badr);
                MMA16816(acc[0][jn * 2],     ah[0], bh[0], bh[1]);
                MMA16816(acc[1][jn * 2],     ah[1], bh[0], bh[1]);
                MMA16816(acc[0][jn * 2 + 1], ah[0], bh[2], bh[3]);
                MMA16816(acc[1][jn * 2 + 1], ah[1], bh[2], bh[3]);
                MMA16816(acc[0][jn * 2],     al[0], bh[0], bh[1]);
                MMA16816(acc[1][jn * 2],     al[1], bh[0], bh[1]);
                MMA16816(acc[0][jn * 2 + 1], al[0], bh[2], bh[3]);
                MMA16816(acc[1][jn * 2 + 1], al[1], bh[2], bh[3]);
                badr = uBl + (uint32_t)(((ks * 16 + b_row) * BPAD + b_col + jn * 16) * 2);
                LDSM4T(bl, badr);
                MMA16816(acc[0][jn * 2],     ah[0], bl[0], bl[1]);
                MMA16816(acc[1][jn * 2],     ah[1], bl[0], bl[1]);
                MMA16816(acc[0][jn * 2 + 1], ah[0], bl[2], bl[3]);
                MMA16816(acc[1][jn * 2 + 1], ah[1], bl[2], bl[3]);
            }
        }
    }

    // ---- epilogue: store raw fp32 + fused per-channel stats ----
    const int gr = lane >> 2, qc = (lane & 3) * 2;
#pragma unroll
    for (int t = 0; t < 2; t++) {
        int ch0 = m0 + wm + t * 16 + gr;          // rows gr and gr+8
        float s0 = 0.f, q0 = 0.f, s1 = 0.f, q1 = 0.f;
        float* base0 = dst + ((size_t)b * 256 + ch0) * Npts + n0 + wn + qc;
        float* base1 = base0 + 8 * (size_t)Npts;
#pragma unroll
        for (int j = 0; j < 8; j++) {
            float2 v = {acc[t][j][0], acc[t][j][1]};
            *(float2*)(base0 + j * 8) = v;
            s0 += v.x + v.y; q0 += v.x * v.x + v.y * v.y;
            float2 w = {acc[t][j][2], acc[t][j][3]};
            *(float2*)(base1 + j * 8) = w;
            s1 += w.x + w.y; q1 += w.x * w.x + w.y * w.y;
        }
#pragma unroll
        for (int o = 1; o < 4; o <<= 1) {
            s0 += __shfl_xor_sync(0xffffffffu, s0, o);
            q0 += __shfl_xor_sync(0xffffffffu, q0, o);
            s1 += __shfl_xor_sync(0xffffffffu, s1, o);
            q1 += __shfl_xor_sync(0xffffffffu, q1, o);
        }
        if ((lane & 3) == 0) {
            atomicAdd(sum + ch0, s0);      atomicAdd(sq + ch0, q0);
            atomicAdd(sum + ch0 + 8, s1);  atomicAdd(sq + ch0 + 8, q1);
        }
    }
}

// ---------------- final BN2 + ReLU in place on d_out ----------------
__global__ void bnrelu_kernel(float* __restrict__ out) {
    size_t i = (size_t)blockIdx.x * 256 + threadIdx.x;   // float4 index
    int c = (int)((i / (Npts / 4)) & (COUT - 1));
    float a = g_a1[c], be = g_be1[c];
    float4 v = ((float4*)out)[i];
    v.x = fmaxf(fmaf(a, v.x, be), 0.f);
    v.y = fmaxf(fmaf(a, v.y, be), 0.f);
    v.z = fmaxf(fmaf(a, v.z, be), 0.f);
    v.w = fmaxf(fmaf(a, v.w, be), 0.f);
    ((float4*)out)[i] = v;
}

// ---------------- launch ----------------
extern "C" void kernel_launch(void* const* d_in, const int* in_sizes, int n_in,
                              void* d_out, int out_size) {
    const float* xyz1    = (const float*)d_in[0];
    const float* xyz2    = (const float*)d_in[1];
    const float* points1 = (const float*)d_in[2];
    const float* points2 = (const float*)d_in[3];
    const float* w0      = (const float*)d_in[4];
    const float* g0      = (const float*)d_in[6];
    const float* be0     = (const float*)d_in[7];
    const float* w1      = (const float*)d_in[8];
    const float* g1      = (const float*)d_in[10];
    const float* be1     = (const float*)d_in[11];
    float* out = (float*)d_out;

    split_w_kernel<<<(CMID * CIN + 255) / 256, 256>>>(w0, 0, CMID * CIN);
    split_w_kernel<<<(COUT * CMID + 255) / 256, 256>>>(w1, 1, COUT * CMID);
    transpose_p2_kernel<<<dim3(Spts / 32, Dfeat / 32, Bsz), dim3(32, 8)>>>(points2);
    knn_kernel<<<dim3(Npts / 256, Bsz), 256>>>(xyz1, xyz2);
    interp_kernel<<<dim3(Npts / 32, Bsz), 256>>>();
    zero_stats_kernel<<<1, 256>>>();
    gemm_mma_kernel<<<dim3(Npts / 128, 2, Bsz), 256>>>(0, points1, out);
    finalize0_kernel<<<1, CMID>>>(g0, be0);
    gemm_mma_kernel<<<dim3(Npts / 128, 2, Bsz), 256>>>(1, points1, out);
    finalize1_kernel<<<1, COUT>>>(g1, be1);
    bnrelu_kernel<<<(int)(((size_t)Bsz * COUT * Npts / 4) / 256), 256>>>(out);
}

// round 11
// speedup vs baseline: 2.6236x; 1.2286x over previous
#include <cuda_runtime.h>
#include <cuda_fp16.h>
#include <cstdint>

#define Bsz   8
#define Npts  16384
#define Spts  1024
#define Dfeat 256
#define CIN   512
#define CMID  256
#define COUT  256
#define CNT_INV (1.0f / (8.0f * 16384.0f))

// ---------------- scratch (device globals; no runtime allocation) ----------------
__device__ __align__(128) float g_p2t[Bsz * Spts * Dfeat];            // points2^T [B,S,D]
__device__ float g_w3[Bsz * Npts * 3];
__device__ int   g_i3[Bsz * Npts * 3];
__device__ __align__(128) __half g_ih[(size_t)Bsz * Dfeat * Npts];    // interp [B,D,N] fp16
__device__ __align__(128) __half g_y0h[(size_t)Bsz * CMID * Npts];    // raw GEMM1 out fp16
__device__ __align__(128) __half g_w0h[CMID * CIN], g_w0l[CMID * CIN];
__device__ __align__(128) __half g_w1h[COUT * CMID], g_w1l[COUT * CMID];
__device__ float g_sum0[CMID], g_sq0[CMID], g_sum1[COUT], g_sq1[COUT];
__device__ float g_a0[CMID], g_be0[CMID], g_a1[COUT], g_be1[COUT];

// ---------------- helpers ----------------
__device__ __forceinline__ uint32_t smem_u32(const void* p) {
    uint32_t a;
    asm("{ .reg .u64 t; cvta.to.shared.u64 t, %1; cvt.u32.u64 %0, t; }" : "=r"(a) : "l"(p));
    return a;
}
#define LDSM4(R, A) \
    asm volatile("ldmatrix.sync.aligned.m8n8.x4.shared.b16 {%0,%1,%2,%3}, [%4];" \
        : "=r"((R)[0]), "=r"((R)[1]), "=r"((R)[2]), "=r"((R)[3]) : "r"(A))
#define LDSM4T(R, A) \
    asm volatile("ldmatrix.sync.aligned.m8n8.x4.trans.shared.b16 {%0,%1,%2,%3}, [%4];" \
        : "=r"((R)[0]), "=r"((R)[1]), "=r"((R)[2]), "=r"((R)[3]) : "r"(A))
#define MMA16816(C, A, B0, B1) \
    asm volatile("mma.sync.aligned.m16n8k16.row.col.f32.f16.f16.f32 " \
        "{%0,%1,%2,%3}, {%4,%5,%6,%7}, {%8,%9}, {%0,%1,%2,%3};" \
        : "+f"((C)[0]), "+f"((C)[1]), "+f"((C)[2]), "+f"((C)[3]) \
        : "r"((A)[0]), "r"((A)[1]), "r"((A)[2]), "r"((A)[3]), "r"(B0), "r"(B1))

// ---------------- transpose points2 [B,D,S] -> [B,S,D] ----------------
__global__ void transpose_p2_kernel(const float* __restrict__ p2) {
    __shared__ float t[32][33];
    int b = blockIdx.z, s0 = blockIdx.x * 32, d0 = blockIdx.y * 32;
    int tx = threadIdx.x, ty = threadIdx.y;
    const float* src = p2 + (size_t)b * Dfeat * Spts;
#pragma unroll
    for (int j = 0; j < 32; j += 8)
        t[ty + j][tx] = src[(size_t)(d0 + ty + j) * Spts + s0 + tx];
    __syncthreads();
    float* dst = g_p2t + (size_t)b * Spts * Dfeat;
#pragma unroll
    for (int j = 0; j < 32; j += 8)
        dst[(size_t)(s0 + ty + j) * Dfeat + d0 + tx] = t[tx][ty + j];
}

// ---------------- 3-NN + inverse-distance weights (3-FFMA inner loop) ----------------
__global__ void knn_kernel(const float* __restrict__ xyz1, const float* __restrict__ xyz2) {
    __shared__ float4 sP[Spts];    // {-2x, -2y, -2z, |x|^2}
    int b = blockIdx.y;
    int n = blockIdx.x * blockDim.x + threadIdx.x;
    const float* x2 = xyz2 + (size_t)b * 3 * Spts;
    for (int s = threadIdx.x; s < Spts; s += blockDim.x) {
        float X = x2[s], Y = x2[Spts + s], Z = x2[2 * Spts + s];
        sP[s] = make_float4(-2.f * X, -2.f * Y, -2.f * Z, X * X + Y * Y + Z * Z);
    }
    __syncthreads();
    const float* x1 = xyz1 + (size_t)b * 3 * Npts;
    float px = x1[n], py = x1[Npts + n], pz = x1[2 * Npts + n];
    float n1 = px * px + py * py + pz * pz;
    // selection on d' = d - n1 (same ordering; n1 re-added at the end)
    float d0 = 3.4e38f, d1 = 3.4e38f, d2 = 3.4e38f;
    int   i0 = 0, i1 = 0, i2 = 0;
#pragma unroll 8
    for (int s = 0; s < Spts; s++) {
        float4 q = sP[s];
        float d = fmaf(q.x, px, fmaf(q.y, py, fmaf(q.z, pz, q.w)));
        if (d < d2) {
            if (d < d1) {
                d2 = d1; i2 = i1;
                if (d < d0) { d1 = d0; i1 = i0; d0 = d; i0 = s; }
                else        { d1 = d;  i1 = s; }
            } else { d2 = d; i2 = s; }
        }
    }
    float r0 = 1.0f / (d0 + n1 + 1e-8f);
    float r1 = 1.0f / (d1 + n1 + 1e-8f);
    float r2 = 1.0f / (d2 + n1 + 1e-8f);
    float rs = 1.0f / (r0 + r1 + r2);
    int o = (b * Npts + n) * 3;
    g_w3[o] = r0 * rs; g_w3[o + 1] = r1 * rs; g_w3[o + 2] = r2 * rs;
    g_i3[o] = i0;      g_i3[o + 1] = i1;      g_i3[o + 2] = i2;
}

// ---------------- interpolation -> g_ih [B,D,N] fp16 ----------------
__global__ void interp_kernel() {
    __shared__ float tile[256 * 33];
    int b   = blockIdx.y;
    int n0  = blockIdx.x * 32;
    int tid = threadIdx.x, lane = tid & 31, wid = tid >> 5;
#pragma unroll
    for (int p = 0; p < 4; p++) {
        int nloc = wid * 4 + p;
        int n    = n0 + nloc;
        int base = (b * Npts + n) * 3;
        float w0 = g_w3[base], w1 = g_w3[base + 1], w2 = g_w3[base + 2];
        const float* r0 = g_p2t + ((size_t)b * Spts + g_i3[base])     * Dfeat;
        const float* r1 = g_p2t + ((size_t)b * Spts + g_i3[base + 1]) * Dfeat;
        const float* r2 = g_p2t + ((size_t)b * Spts + g_i3[base + 2]) * Dfeat;
#pragma unroll
        for (int j = 0; j < 8; j++) {
            int d = lane + 32 * j;
            tile[d * 33 + nloc] = w0 * r0[d] + w1 * r1[d] + w2 * r2[d];
        }
    }
    __syncthreads();
    __half* outb = g_ih + (size_t)b * Dfeat * Npts;
#pragma unroll 4
    for (int e = tid; e < 256 * 32; e += 256) {
        int d = e >> 5, nl = e & 31;
        outb[(size_t)d * Npts + n0 + nl] = __float2half_rn(tile[d * 33 + nl]);
    }
}

// ---------------- weight split fp32 -> fp16 hi/lo ----------------
__global__ void split_w_kernel(const float* __restrict__ src, int which, int n) {
    int i = blockIdx.x * 256 + threadIdx.x;
    if (i >= n) return;
    float v = src[i];
    __half h = __float2half_rn(v);
    __half l = __float2half_rn(v - __half2float(h));
    if (which) { g_w1h[i] = h; g_w1l[i] = l; }
    else       { g_w0h[i] = h; g_w0l[i] = l; }
}

// ---------------- stats zero / finalize ----------------
__global__ void zero_stats_kernel() {
    int t = threadIdx.x;
    g_sum0[t] = 0.f; g_sq0[t] = 0.f; g_sum1[t] = 0.f; g_sq1[t] = 0.f;
}
__global__ void finalize0_kernel(const float* __restrict__ g, const float* __restrict__ be) {
    int c = threadIdx.x;
    float mean = g_sum0[c] * CNT_INV;
    float var  = g_sq0[c] * CNT_INV - mean * mean;
    float a    = g[c] * rsqrtf(var + 1e-5f);
    g_a0[c] = a; g_be0[c] = be[c] - mean * a;
}
__global__ void finalize1_kernel(const float* __restrict__ g, const float* __restrict__ be) {
    int c = threadIdx.x;
    float mean = g_sum1[c] * CNT_INV;
    float var  = g_sq1[c] * CNT_INV - mean * mean;
    float a    = g[c] * rsqrtf(var + 1e-5f);
    g_a1[c] = a; g_be1[c] = be[c] - mean * a;
}

// ---------------- fp16 2-term HMMA GEMM ----------------
// out[M=256, N=16384] = W @ X per batch. CTA tile 128M x 128N, K-chunk 32.
// acc = (Wh + Wl) @ fp16(X): dropped error is W*(X - fp16(X)) ~ 2^-12 relative.
// which=0: X = points1/interp, dst = g_y0h (fp16), stats0.
// which=1: X = relu(bn1(y0)),  dst = out (fp32),  stats1.
#define APAD 40
#define BPAD 136
__global__ __launch_bounds__(256, 2)
void gemm_mma_kernel(int which, const float* __restrict__ p1, float* __restrict__ outp) {
    __shared__ __half sAh[128 * APAD];
    __shared__ __half sAl[128 * APAD];
    __shared__ __half sB[32 * BPAD];

    const int K   = which ? CMID : CIN;
    const int tid = threadIdx.x;
    const int lane = tid & 31, warp = tid >> 5;
    const int b  = blockIdx.z;
    const int m0 = blockIdx.x * 128;     // x = m-tile so n-tile pairs are adjacent in block id
    const int n0 = blockIdx.y * 128;
    const int wm = (warp >> 1) * 32;
    const int wn = (warp & 1) * 64;

    const __half* Wh = which ? g_w1h : g_w0h;
    const __half* Wl = which ? g_w1l : g_w0l;
    float* sum = which ? g_sum1 : g_sum0;
    float* sq  = which ? g_sq1  : g_sq0;

    float acc[2][8][4];
#pragma unroll
    for (int t = 0; t < 2; t++)
#pragma unroll
        for (int j = 0; j < 8; j++)
#pragma unroll
            for (int q = 0; q < 4; q++) acc[t][j][q] = 0.f;

    const uint32_t uAh = smem_u32(sAh), uAl = smem_u32(sAl);
    const uint32_t uB  = smem_u32(sB);
    const int a_row = wm + (lane & 15);
    const int a_col = (lane >> 4) * 8;
    const int b_row = (lane & 15);
    const int b_col = wn + (lane >> 4) * 8;

    for (int k0 = 0; k0 < K; k0 += 32) {
        __syncthreads();
        // ---- stage A (weights fp16 hi/lo) ----
#pragma unroll
        for (int i = 0; i < 2; i++) {
            int idx = i * 256 + tid;
            int r = idx >> 2, q = (idx & 3) * 8;
            size_t go = (size_t)(m0 + r) * K + k0 + q;
            *(uint4*)&sAh[r * APAD + q] = *(const uint4*)(Wh + go);
            *(uint4*)&sAl[r * APAD + q] = *(const uint4*)(Wl + go);
        }
        // ---- stage B: single fp16 ----
#pragma unroll
        for (int i = 0; i < 2; i++) {
            int idx = i * 256 + tid;
            int r = idx >> 4, c = (idx & 15) * 8;
            int k = k0 + r;
            uint4 pk;
            if (which) {
                uint4 raw = *(const uint4*)(g_y0h + ((size_t)b * CMID + k) * Npts + n0 + c);
                float a = g_a0[k], be = g_be0[k];
                __half2* hp = (__half2*)&raw;
                uint32_t o[4];
#pragma unroll
                for (int j = 0; j < 4; j++) {
                    float2 f = __half22float2(hp[j]);
                    f.x = fmaxf(fmaf(a, f.x, be), 0.f);
                    f.y = fmaxf(fmaf(a, f.y, be), 0.f);
                    __half2 h = __floats2half2_rn(f.x, f.y);
                    o[j] = *(uint32_t*)&h;
                }
                pk = make_uint4(o[0], o[1], o[2], o[3]);
            } else if (k < Dfeat) {
                const float* src = p1 + ((size_t)b * Dfeat + k) * Npts + n0 + c;
                float4 v0 = *(const float4*)src;
                float4 v1 = *(const float4*)(src + 4);
                __half2 h0 = __floats2half2_rn(v0.x, v0.y);
                __half2 h1 = __floats2half2_rn(v0.z, v0.w);
                __half2 h2 = __floats2half2_rn(v1.x, v1.y);
                __half2 h3 = __floats2half2_rn(v1.z, v1.w);
                pk = make_uint4(*(uint32_t*)&h0, *(uint32_t*)&h1,
                                *(uint32_t*)&h2, *(uint32_t*)&h3);
            } else {
                pk = *(const uint4*)(g_ih + ((size_t)b * Dfeat + (k - Dfeat)) * Npts + n0 + c);
            }
            *(uint4*)&sB[r * BPAD + c] = pk;
        }
        __syncthreads();
        // ---- MMA: Wh*B + Wl*B ----
#pragma unroll
        for (int ks = 0; ks < 2; ks++) {
            uint32_t ah[2][4], al[2][4];
#pragma unroll
            for (int t = 0; t < 2; t++) {
                uint32_t adr = uAh + (uint32_t)(((a_row + t * 16) * APAD + ks * 16 + a_col) * 2);
                LDSM4(ah[t], adr);
                adr = uAl + (uint32_t)(((a_row + t * 16) * APAD + ks * 16 + a_col) * 2);
                LDSM4(al[t], adr);
            }
#pragma unroll
            for (int jn = 0; jn < 4; jn++) {
                uint32_t bh[4];
                uint32_t badr = uB + (uint32_t)(((ks * 16 + b_row) * BPAD + b_col + jn * 16) * 2);
                LDSM4T(bh, badr);
                MMA16816(acc[0][jn * 2],     ah[0], bh[0], bh[1]);
                MMA16816(acc[1][jn * 2],     ah[1], bh[0], bh[1]);
                MMA16816(acc[0][jn * 2 + 1], ah[0], bh[2], bh[3]);
                MMA16816(acc[1][jn * 2 + 1], ah[1], bh[2], bh[3]);
                MMA16816(acc[0][jn * 2],     al[0], bh[0], bh[1]);
                MMA16816(acc[1][jn * 2],     al[1], bh[0], bh[1]);
                MMA16816(acc[0][jn * 2 + 1], al[0], bh[2], bh[3]);
                MMA16816(acc[1][jn * 2 + 1], al[1], bh[2], bh[3]);
            }
        }
    }

    // ---- epilogue: store (fp16 y0 | fp32 out) + fused per-channel stats ----
    const int gr = lane >> 2, qc = (lane & 3) * 2;
#pragma unroll
    for (int t = 0; t < 2; t++) {
        int ch0 = m0 + wm + t * 16 + gr;          // rows gr and gr+8
        float s0 = 0.f, q0 = 0.f, s1 = 0.f, q1 = 0.f;
        size_t col = (size_t)n0 + wn + qc;
#pragma unroll
        for (int j = 0; j < 8; j++) {
            float2 v = {acc[t][j][0], acc[t][j][1]};
            float2 w = {acc[t][j][2], acc[t][j][3]};
            s0 += v.x + v.y; q0 += v.x * v.x + v.y * v.y;
            s1 += w.x + w.y; q1 += w.x * w.x + w.y * w.y;
            if (which) {
                float* b0p = outp + ((size_t)b * 256 + ch0) * Npts + col + j * 8;
                *(float2*)b0p = v;
                *(float2*)(b0p + 8 * (size_t)Npts) = w;
            } else {
                __half* b0p = g_y0h + ((size_t)b * 256 + ch0) * Npts + col + j * 8;
                *(__half2*)b0p = __floats2half2_rn(v.x, v.y);
                *(__half2*)(b0p + 8 * (size_t)Npts) = __floats2half2_rn(w.x, w.y);
            }
        }
#pragma unroll
        for (int o = 1; o < 4; o <<= 1) {
            s0 += __shfl_xor_sync(0xffffffffu, s0, o);
            q0 += __shfl_xor_sync(0xffffffffu, q0, o);
            s1 += __shfl_xor_sync(0xffffffffu, s1, o);
            q1 += __shfl_xor_sync(0xffffffffu, q1, o);
        }
        if ((lane & 3) == 0) {
            atomicAdd(sum + ch0, s0);      atomicAdd(sq + ch0, q0);
            atomicAdd(sum + ch0 + 8, s1);  atomicAdd(sq + ch0 + 8, q1);
        }
    }
}

// ---------------- final BN2 + ReLU in place on d_out ----------------
__global__ void bnrelu_kernel(float* __restrict__ out) {
    size_t i = (size_t)blockIdx.x * 256 + threadIdx.x;   // float4 index
    int c = (int)((i / (Npts / 4)) & (COUT - 1));
    float a = g_a1[c], be = g_be1[c];
    float4 v = ((float4*)out)[i];
    v.x = fmaxf(fmaf(a, v.x, be), 0.f);
    v.y = fmaxf(fmaf(a, v.y, be), 0.f);
    v.z = fmaxf(fmaf(a, v.z, be), 0.f);
    v.w = fmaxf(fmaf(a, v.w, be), 0.f);
    ((float4*)out)[i] = v;
}

// ---------------- launch ----------------
extern "C" void kernel_launch(void* const* d_in, const int* in_sizes, int n_in,
                              void* d_out, int out_size) {
    const float* xyz1    = (const float*)d_in[0];
    const float* xyz2    = (const float*)d_in[1];
    const float* points1 = (const float*)d_in[2];
    const float* points2 = (const float*)d_in[3];
    const float* w0      = (const float*)d_in[4];
    const float* g0      = (const float*)d_in[6];
    const float* be0     = (const float*)d_in[7];
    const float* w1      = (const float*)d_in[8];
    const float* g1      = (const float*)d_in[10];
    const float* be1     = (const float*)d_in[11];
    float* out = (float*)d_out;

    split_w_kernel<<<(CMID * CIN + 255) / 256, 256>>>(w0, 0, CMID * CIN);
    split_w_kernel<<<(COUT * CMID + 255) / 256, 256>>>(w1, 1, COUT * CMID);
    transpose_p2_kernel<<<dim3(Spts / 32, Dfeat / 32, Bsz), dim3(32, 8)>>>(points2);
    knn_kernel<<<dim3(Npts / 256, Bsz), 256>>>(xyz1, xyz2);
    interp_kernel<<<dim3(Npts / 32, Bsz), 256>>>();
    zero_stats_kernel<<<1, 256>>>();
    gemm_mma_kernel<<<dim3(2, Npts / 128, Bsz), 256>>>(0, points1, out);
    finalize0_kernel<<<1, CMID>>>(g0, be0);
    gemm_mma_kernel<<<dim3(2, Npts / 128, Bsz), 256>>>(1, points1, out);
    finalize1_kernel<<<1, COUT>>>(g1, be1);
    bnrelu_kernel<<<(int)(((size_t)Bsz * COUT * Npts / 4) / 256), 256>>>(out);
}